// round 5
// baseline (speedup 1.0000x reference)
#include <cuda_runtime.h>
#include <cstdint>

// Problem dims
#define BN    128   // batch
#define TT    512   // timesteps
#define NR    512   // n_rec (= n_init = n_out)
#define NOUT  512
#define PM    4     // batch groups
#define PN    32    // neuron-slice CTAs per group
#define MB    32    // batch rows per CTA
#define NJ    16    // neurons per CTA
#define NTH   256
#define DT_TAU 0.2f

typedef unsigned long long u64;

// ---------------- global scratch (static device arrays; no allocation) ------
__device__ float g_h[BN * NR];
__device__ float g_rh[BN * NR];
__device__ unsigned g_cnt[PM];
__device__ volatile unsigned g_gen[PM];

// ---------------- f32x2 helpers (u64 carries a packed float2) ---------------
__device__ __forceinline__ u64 ffma2(u64 a, u64 b, u64 c) {
    u64 d;
    asm("fma.rn.f32x2 %0, %1, %2, %3;" : "=l"(d) : "l"(a), "l"(b), "l"(c));
    return d;
}
__device__ __forceinline__ u64 addf2(u64 a, u64 b) {
    u64 d;
    asm("add.rn.f32x2 %0, %1, %2;" : "=l"(d) : "l"(a), "l"(b));
    return d;
}
__device__ __forceinline__ u64 pack2(float lo, float hi) {
    u64 d;
    asm("mov.b64 %0, {%1, %2};" : "=l"(d) : "f"(lo), "f"(hi));
    return d;
}
__device__ __forceinline__ float2 unpack2(u64 d) {
    float2 r;
    asm("mov.b64 {%0, %1}, %2;" : "=f"(r.x), "=f"(r.y) : "l"(d));
    return r;
}

// ---------------- SMEM layout (byte offsets) --------------------------------
// WZR : [k][16 neurons x {z,r}] interleaved floats  : 512*32*4  = 65536
// WH2 : [jp][k] packed-pair u64, row 514 u64        : 8*514*8   = 32896
// HS  : 32 rows x (512 floats + 16B pad)            : 32*2064   = 66048
// XT  : 32 float2                                   : 256
// WZRX: 2 x 16 packed u64                           : 256
// WHX : 2 x 8 packed u64                            : 128
#define WZR_OFF   0
#define WH2_OFF   65536
#define WH2_ROWD  514
#define HS_OFF    (WH2_OFF + 8 * WH2_ROWD * 8)            // 98432
#define HS_STRIDE 2064
#define XT_OFF    (HS_OFF + MB * HS_STRIDE)               // 164480
#define WZRX_OFF  (XT_OFF + 256)                          // 164736
#define WHX_OFF   (WZRX_OFF + 256)                        // 164992
#define SMEM_TOTAL (WHX_OFF + 128)                        // 165120

// ---------------- group barrier (monotonic count, launch-reset) -------------
__device__ __forceinline__ void group_barrier(int g, unsigned& idx) {
    __syncthreads();
    if (threadIdx.x == 0) {
        __threadfence();  // release: publish this CTA's global writes
        unsigned old = atomicAdd(&g_cnt[g], 1u);
        if (old == idx * (unsigned)PN + (PN - 1)) {
            __threadfence();
            g_gen[g] = idx + 1u;
        } else {
            while (g_gen[g] < idx + 1u) {}
            __threadfence();  // acquire
        }
    }
    __syncthreads();
    idx++;
}

__global__ void init_bar_kernel() {
    int i = threadIdx.x;
    if (i < PM) { g_cnt[i] = 0u; g_gen[i] = 0u; }
}

// ---------------- staging: 32 rows x 512 floats, gmem -> padded SMEM --------
// CG=true  -> __ldcg (L2-only; for cross-SM-produced g_h / g_rh)
template <bool CG>
__device__ __forceinline__ void stage_rows(const float* __restrict__ src,
                                           char* smem, int b0, int tid) {
    int row = tid >> 3;
    int c0  = tid & 7;
    const float4* s = (const float4*)(src + (size_t)(b0 + row) * NR) + c0;
    float4* d = (float4*)(smem + HS_OFF + row * HS_STRIDE) + c0;
#pragma unroll
    for (int i = 0; i < 16; i++) d[8 * i] = CG ? __ldcg(s + 8 * i) : s[8 * i];
}

// dot over K=512: acc{pair} += sum_k v[k] * {W[jj0,k], W[jj1,k]}
// w = WH2-layout base for this jp (ulonglong2, k-vectorized, conflict-free)
__device__ __forceinline__ u64 dot512(const float4* __restrict__ hr4,
                                      const ulonglong2* __restrict__ w,
                                      u64 init) {
    u64 u = init, ub = 0ull;
#pragma unroll 8
    for (int k4 = 0; k4 < 128; k4++) {
        float4 v = hr4[k4];
        ulonglong2 wa = w[2 * k4];
        ulonglong2 wb = w[2 * k4 + 1];
        u  = ffma2(pack2(v.x, v.x), wa.x, u);
        ub = ffma2(pack2(v.y, v.y), wa.y, ub);
        u  = ffma2(pack2(v.z, v.z), wb.x, u);
        ub = ffma2(pack2(v.w, v.w), wb.y, ub);
    }
    return addf2(u, ub);
}

// ---------------- persistent recurrent kernel -------------------------------
__global__ void __launch_bounds__(NTH, 1)
rnn_persistent(const float* __restrict__ x, const float* __restrict__ init_state,
               const float* __restrict__ W_enc, const float* __restrict__ W_wz,
               const float* __restrict__ W_uz, const float* __restrict__ W_wr,
               const float* __restrict__ W_ur, const float* __restrict__ W_wh,
               const float* __restrict__ W_uh, float* __restrict__ out_h) {
    extern __shared__ char smem[];
    const int tid = threadIdx.x;
    const int gm = blockIdx.x & 3;   // batch group
    const int gn = blockIdx.x >> 2;  // neuron slice
    const int b0 = gm * MB;
    const int j0 = gn * NJ;
    const int jp = tid & 7;          // neuron-pair index (2 neurons)
    const int bb = tid >> 3;         // local batch row
    const int jj0 = 2 * jp;
    unsigned bidx = 0;

    float*  WZRf = (float*)(smem + WZR_OFF);
    float*  WH2f = (float*)(smem + WH2_OFF);
    const ulonglong2* WZRd2 = (const ulonglong2*)(smem + WZR_OFF);
    const ulonglong2* WHrow =
        (const ulonglong2*)(smem + WH2_OFF) + jp * (WH2_ROWD / 2);
    u64* wzrx = (u64*)(smem + WZRX_OFF);
    u64* whx  = (u64*)(smem + WHX_OFF);
    float2* xts = (float2*)(smem + XT_OFF);
    const float4* hrow4 = (const float4*)(smem + HS_OFF + bb * HS_STRIDE);

    // ---- h0 = init_state @ W_enc^T  (W_enc slice staged in WH2 layout) ----
    for (int idx = tid; idx < 8 * NR; idx += NTH) {
        int p = idx >> 9, k = idx & 511;
        WH2f[p * 2 * WH2_ROWD + 2 * k]     = W_enc[(size_t)(j0 + 2 * p) * NR + k];
        WH2f[p * 2 * WH2_ROWD + 2 * k + 1] = W_enc[(size_t)(j0 + 2 * p + 1) * NR + k];
    }
    stage_rows<false>(init_state, smem, b0, tid);
    __syncthreads();
    {
        u64 h0d = dot512(hrow4, WHrow, 0ull);
        *(float2*)&g_h[(size_t)(b0 + bb) * NR + j0 + jj0] = unpack2(h0d);
    }
    __syncthreads();  // all reads of WH2/HS done before overwrite

    // ---- load stationary recurrent weights ----
    for (int idx = tid; idx < NJ * NR; idx += NTH) {
        int jj = idx >> 9, k = idx & 511;
        WZRf[k * 32 + 2 * jj]     = W_uz[(size_t)(j0 + jj) * NR + k];
        WZRf[k * 32 + 2 * jj + 1] = W_ur[(size_t)(j0 + jj) * NR + k];
    }
    for (int idx = tid; idx < 8 * NR; idx += NTH) {
        int p = idx >> 9, k = idx & 511;
        WH2f[p * 2 * WH2_ROWD + 2 * k]     = W_uh[(size_t)(j0 + 2 * p) * NR + k];
        WH2f[p * 2 * WH2_ROWD + 2 * k + 1] = W_uh[(size_t)(j0 + 2 * p + 1) * NR + k];
    }
    if (tid < 16) {
        wzrx[tid]      = pack2(W_wz[(j0 + tid) * 2 + 0], W_wr[(j0 + tid) * 2 + 0]);
        wzrx[16 + tid] = pack2(W_wz[(j0 + tid) * 2 + 1], W_wr[(j0 + tid) * 2 + 1]);
    }
    if (tid < 8) {
        whx[tid]     = pack2(W_wh[(j0 + 2 * tid) * 2 + 0], W_wh[(j0 + 2 * tid + 1) * 2 + 0]);
        whx[8 + tid] = pack2(W_wh[(j0 + 2 * tid) * 2 + 1], W_wh[(j0 + 2 * tid + 1) * 2 + 1]);
    }
    group_barrier(gm, bidx);  // h0 visible group-wide; weights loaded

    for (int t = 0; t < TT; t++) {
        // ---------------- phase 1: z, r, r*h ----------------
        if (tid < MB)
            xts[tid] = ((const float2*)x)[(size_t)(b0 + tid) * TT + t];
        stage_rows<true>(g_h, smem, b0, tid);
        __syncthreads();

        float2 xt = xts[bb];
        u64 x0p = pack2(xt.x, xt.x), x1p = pack2(xt.y, xt.y);
        u64 a0 = ffma2(x0p, wzrx[jj0],     ffma2(x1p, wzrx[16 + jj0], 0ull));
        u64 a1 = ffma2(x0p, wzrx[jj0 + 1], ffma2(x1p, wzrx[16 + jj0 + 1], 0ull));
        u64 a0b = 0ull, a1b = 0ull;
        const ulonglong2* wz = WZRd2 + jp;
#pragma unroll 8
        for (int k4 = 0; k4 < 128; k4++) {
            float4 hv = hrow4[k4];
            u64 hx = pack2(hv.x, hv.x);
            ulonglong2 w0 = wz[(4 * k4 + 0) * 8];
            a0  = ffma2(hx, w0.x, a0);  a1  = ffma2(hx, w0.y, a1);
            u64 hy = pack2(hv.y, hv.y);
            ulonglong2 w1 = wz[(4 * k4 + 1) * 8];
            a0b = ffma2(hy, w1.x, a0b); a1b = ffma2(hy, w1.y, a1b);
            u64 hz = pack2(hv.z, hv.z);
            ulonglong2 w2 = wz[(4 * k4 + 2) * 8];
            a0  = ffma2(hz, w2.x, a0);  a1  = ffma2(hz, w2.y, a1);
            u64 hw = pack2(hv.w, hv.w);
            ulonglong2 w3 = wz[(4 * k4 + 3) * 8];
            a0b = ffma2(hw, w3.x, a0b); a1b = ffma2(hw, w3.y, a1b);
        }
        a0 = addf2(a0, a0b);
        a1 = addf2(a1, a1b);
        float2 zr0 = unpack2(a0), zr1 = unpack2(a1);
        float z0 = 1.f / (1.f + __expf(-zr0.x));
        float r0 = 1.f / (1.f + __expf(-zr0.y));
        float z1 = 1.f / (1.f + __expf(-zr1.x));
        float r1 = 1.f / (1.f + __expf(-zr1.y));
        float2 hown = *(const float2*)(smem + HS_OFF + bb * HS_STRIDE +
                                       (size_t)(j0 + jj0) * 4);
        float2 rh;
        rh.x = r0 * hown.x;
        rh.y = r1 * hown.y;
        *(float2*)&g_rh[(size_t)(b0 + bb) * NR + j0 + jj0] = rh;

        group_barrier(gm, bidx);  // rh visible group-wide

        // ---------------- phase 2: u, tanh, h update ----------------
        stage_rows<true>(g_rh, smem, b0, tid);
        __syncthreads();

        u64 ui = ffma2(x0p, whx[jp], ffma2(x1p, whx[8 + jp], 0ull));
        u64 ud = dot512(hrow4, WHrow, ui);
        float2 uf = unpack2(ud);
        float th0 = tanhf(uf.x), th1 = tanhf(uf.y);
        float2 hn;
        hn.x = hown.x + DT_TAU * (z0 - 1.f) * (hown.x - th0);
        hn.y = hown.y + DT_TAU * (z1 - 1.f) * (hown.y - th1);
        *(float2*)&g_h[(size_t)(b0 + bb) * NR + j0 + jj0] = hn;
        *(float2*)&out_h[((size_t)(b0 + bb) * TT + t) * NR + j0 + jj0] = hn;

        group_barrier(gm, bidx);  // h_new visible group-wide
    }
}

// ---------------- decoder: y = h @ W_dec^T  (f32x2 tiled GEMM) --------------
// Tile: 128 (BT rows) x 64 (out cols), K chunks of 32. 256 threads.
// Thread: 4 rowpairs (rows 2rg+32i, +1) x 4 cols.
__global__ void __launch_bounds__(256)
decoder_kernel(const float* __restrict__ h, const float* __restrict__ W,
               float* __restrict__ y) {
    __shared__ float HT[32 * 132];  // [k][row], stride 132
    __shared__ float WT[32 * 68];   // [k][col], stride 68
    const int tid = threadIdx.x;
    const int bt0 = blockIdx.x * 128;
    const int o0  = blockIdx.y * 64;
    const int rg = tid & 15;        // rowpair group
    const int cg = tid >> 4;        // col group (0..15), cols = cg*4..cg*4+3
    const int col0 = cg * 4;
    const int lrow = tid >> 1, lkh = (tid & 1) * 16;
    const int lcol = tid >> 2, lkw = (tid & 3) * 8;

    u64 acc[4][4];
#pragma unroll
    for (int i = 0; i < 4; i++)
#pragma unroll
        for (int c = 0; c < 4; c++) acc[i][c] = 0ull;

    for (int k0 = 0; k0 < NR; k0 += 32) {
        __syncthreads();
        // h tile: transposed store HT[k][row]
        const float4* hsrc =
            (const float4*)(h + (size_t)(bt0 + lrow) * NR + k0 + lkh);
#pragma unroll
        for (int j = 0; j < 4; j++) {
            float4 v = hsrc[j];
            int kk = lkh + 4 * j;
            HT[(kk + 0) * 132 + lrow] = v.x;
            HT[(kk + 1) * 132 + lrow] = v.y;
            HT[(kk + 2) * 132 + lrow] = v.z;
            HT[(kk + 3) * 132 + lrow] = v.w;
        }
        // W tile: transposed store WT[k][col]
        const float4* wsrc =
            (const float4*)(W + (size_t)(o0 + lcol) * NR + k0 + lkw);
#pragma unroll
        for (int j = 0; j < 2; j++) {
            float4 v = wsrc[j];
            int kk = lkw + 4 * j;
            WT[(kk + 0) * 68 + lcol] = v.x;
            WT[(kk + 1) * 68 + lcol] = v.y;
            WT[(kk + 2) * 68 + lcol] = v.z;
            WT[(kk + 3) * 68 + lcol] = v.w;
        }
        __syncthreads();
#pragma unroll 4
        for (int k = 0; k < 32; k++) {
            const u64* HTd = (const u64*)(HT + k * 132);
            u64 h0 = HTd[rg];
            u64 h1 = HTd[rg + 16];
            u64 h2 = HTd[rg + 32];
            u64 h3 = HTd[rg + 48];
            float4 wv = *(const float4*)(WT + k * 68 + col0);
            u64 w0 = pack2(wv.x, wv.x);
            u64 w1 = pack2(wv.y, wv.y);
            u64 w2 = pack2(wv.z, wv.z);
            u64 w3 = pack2(wv.w, wv.w);
            acc[0][0] = ffma2(h0, w0, acc[0][0]);
            acc[0][1] = ffma2(h0, w1, acc[0][1]);
            acc[0][2] = ffma2(h0, w2, acc[0][2]);
            acc[0][3] = ffma2(h0, w3, acc[0][3]);
            acc[1][0] = ffma2(h1, w0, acc[1][0]);
            acc[1][1] = ffma2(h1, w1, acc[1][1]);
            acc[1][2] = ffma2(h1, w2, acc[1][2]);
            acc[1][3] = ffma2(h1, w3, acc[1][3]);
            acc[2][0] = ffma2(h2, w0, acc[2][0]);
            acc[2][1] = ffma2(h2, w1, acc[2][1]);
            acc[2][2] = ffma2(h2, w2, acc[2][2]);
            acc[2][3] = ffma2(h2, w3, acc[2][3]);
            acc[3][0] = ffma2(h3, w0, acc[3][0]);
            acc[3][1] = ffma2(h3, w1, acc[3][1]);
            acc[3][2] = ffma2(h3, w2, acc[3][2]);
            acc[3][3] = ffma2(h3, w3, acc[3][3]);
        }
    }
#pragma unroll
    for (int i = 0; i < 4; i++) {
        int r = 2 * rg + 32 * i;
        float2 p0 = unpack2(acc[i][0]);
        float2 p1 = unpack2(acc[i][1]);
        float2 p2 = unpack2(acc[i][2]);
        float2 p3 = unpack2(acc[i][3]);
        float4 ra = make_float4(p0.x, p1.x, p2.x, p3.x);
        float4 rb = make_float4(p0.y, p1.y, p2.y, p3.y);
        *(float4*)(y + (size_t)(bt0 + r) * NOUT + o0 + col0) = ra;
        *(float4*)(y + (size_t)(bt0 + r + 1) * NOUT + o0 + col0) = rb;
    }
}

// ---------------- launch -----------------------------------------------------
extern "C" void kernel_launch(void* const* d_in, const int* in_sizes, int n_in,
                              void* d_out, int out_size) {
    const float* x          = (const float*)d_in[0];
    const float* init_state = (const float*)d_in[1];
    const float* W_enc      = (const float*)d_in[2];
    const float* W_wz       = (const float*)d_in[3];
    const float* W_uz       = (const float*)d_in[4];
    const float* W_wr       = (const float*)d_in[5];
    const float* W_ur       = (const float*)d_in[6];
    const float* W_wh       = (const float*)d_in[7];
    const float* W_uh       = (const float*)d_in[8];
    const float* W_dec      = (const float*)d_in[9];
    float* out = (float*)d_out;

    cudaFuncSetAttribute(rnn_persistent,
                         cudaFuncAttributeMaxDynamicSharedMemorySize, SMEM_TOTAL);

    init_bar_kernel<<<1, 32>>>();
    rnn_persistent<<<PM * PN, NTH, SMEM_TOTAL>>>(
        x, init_state, W_enc, W_wz, W_uz, W_wr, W_ur, W_wh, W_uh, out);

    size_t hN = (size_t)BN * TT * NR;
    if ((size_t)out_size >= 2 * hN) {
        dim3 grid((BN * TT) / 128, NOUT / 64);
        decoder_kernel<<<grid, 256>>>(out, W_dec, out + hN);
    }
}